// round 14
// baseline (speedup 1.0000x reference)
#include <cuda_runtime.h>
#include <stdint.h>
#include <math.h>

#define NN 16000
#define EE 256000
#define EP (EE+NN)
#define DIN 1280
#define HD 256
#define GG 32
#define OO 64

// rounded-weight scratch layout (floats)
#define FPW_OFF   0
#define WL_OFF    327680
#define WR_OFF    458752
#define GINW_OFF  589824
#define RESW_OFF  720896
#define POOLW_OFF 851968
#define RW_TOT    917504

// dynamic smem for gemm: As[3][128][20] + Bs[3][16][264]
#define AS_STRIDE 2560
#define BS_STRIDE 4224
#define AS_FLOATS (3*AS_STRIDE)
#define BS_FLOATS (3*BS_STRIDE)
#define SMEM_SZ ((AS_FLOATS + BS_FLOATS)*4)

#define CSR_BLOCKS 148

// ---------------- device scratch (static, allocation-free) ----------------
__device__ float d_h0[NN*HD];
__device__ float d_h1[NN*HD];
__device__ float d_xl[NN*HD];
__device__ float d_xr[NN*HD];
__device__ float d_rw[RW_TOT];
__device__ int   d_degGat[NN];
__device__ int   d_ptrGat[NN+1];
__device__ int   d_curGat[NN];
__device__ int   d_colGat[EP];
__device__ float d_red[4];
__device__ float d_gate[NN], d_gsum[GG], d_emb[GG*HD];
__device__ unsigned g_bar = 0;   // monotone ticket counter (never reset)

__device__ __forceinline__ void atomicMaxF(float* addr, float v){
  if (v >= 0.f) atomicMax((int*)addr, __float_as_int(v));
  else          atomicMin((unsigned int*)addr, __float_as_uint(v));
}

__device__ __forceinline__ uint32_t tf32u(float x){
  uint32_t u; asm("cvt.rna.tf32.f32 %0, %1;" : "=r"(u) : "f"(x));
  return u;
}

#define CP16(dst, src) asm volatile("cp.async.cg.shared.global [%0], [%1], 16;\n" :: "r"(dst), "l"(src))
#define CP_COMMIT()    asm volatile("cp.async.commit_group;\n" ::)
template<int N>
__device__ __forceinline__ void cp_wait(){ asm volatile("cp.async.wait_group %0;\n" :: "n"(N)); }

// grid-wide barrier: monotone ticket, all CSR_BLOCKS blocks co-resident.
__device__ __forceinline__ void gridbar(){
  __syncthreads();
  __threadfence();
  if (threadIdx.x == 0){
    unsigned t = atomicAdd(&g_bar, 1) + 1;
    unsigned target = ((t + CSR_BLOCKS - 1) / CSR_BLOCKS) * CSR_BLOCKS;
    for (;;){
      unsigned v;
      asm volatile("ld.global.cg.u32 %0, [%1];" : "=r"(v) : "l"(&g_bar));
      if (v >= target) break;
      __nanosleep(64);
    }
  }
  __syncthreads();
  __threadfence();
}

// ---- fused: init + weight-round + hist + scan + fill (one launch) ----
__global__ __launch_bounds__(1024)
void csr_kernel(const int* __restrict__ ei,
                int* degGat, int* indptr, int* cursor, int* colGat,
                float* red, float* emb, float* gate,
                float* out, const float* __restrict__ head_b2,
                const float* __restrict__ fpW, const float* __restrict__ wl,
                const float* __restrict__ wr, const float* __restrict__ ginw,
                const float* __restrict__ resw, const float* __restrict__ poolw,
                float* __restrict__ rw){
  int gtid = blockIdx.x*blockDim.x + threadIdx.x;
  int gsz  = gridDim.x*blockDim.x;
  // phase 1: init + weight rounding
  for (int i=gtid; i<NN; i+=gsz){ degGat[i]=0; gate[i]=0.f; }
  if (gtid < 4)  red[gtid]=0.f;
  for (int i=gtid; i<GG*HD; i+=gsz) emb[i]=0.f;
  for (int i=gtid; i<GG*OO; i+=gsz) out[i] = head_b2[i % OO];
  for (int idx=gtid; idx<RW_TOT; idx+=gsz){
    float v; int j = idx;
    if (j < 327680) v = fpW[j];
    else { j -= 327680;
      if (j < 131072) v = wl[j];
      else { j -= 131072;
        if (j < 131072) v = wr[j];
        else { j -= 131072;
          if (j < 131072) v = ginw[j];
          else { j -= 131072;
            if (j < 131072) v = resw[j];
            else v = poolw[j-131072];
          }
        }
      }
    }
    rw[idx] = __uint_as_float(tf32u(v));
  }
  gridbar();
  // phase 2: histogram
  for (int e=gtid; e<EP; e+=gsz){
    int dnode = (e < EE) ? ei[EE+e] : (e-EE);
    atomicAdd(&degGat[dnode],1);
  }
  gridbar();
  // phase 3: scan (block 0 only; 1024 threads, 16 elems each)
  if (blockIdx.x == 0){
    int t = threadIdx.x;
    int lane = t & 31, wid = t >> 5;
    const int CH = 16;
    int st = t*CH;
    int dv[CH];
    int mySum = 0;
    #pragma unroll
    for (int i=0;i<CH;i++){
      int idx = st+i;
      dv[i] = (idx<NN)? degGat[idx] : 0;
      mySum += dv[i];
    }
    int inc = mySum;
    #pragma unroll
    for (int off=1; off<32; off<<=1){
      int n = __shfl_up_sync(0xffffffffu, inc, off);
      if (lane >= off) inc += n;
    }
    __shared__ int wtot[32];
    if (lane==31) wtot[wid] = inc;
    __syncthreads();
    if (wid==0){
      int v = wtot[lane];
      #pragma unroll
      for (int off=1; off<32; off<<=1){
        int n = __shfl_up_sync(0xffffffffu, v, off);
        if (lane >= off) v += n;
      }
      wtot[lane] = v;
    }
    __syncthreads();
    int run = inc - mySum + (wid>0 ? wtot[wid-1] : 0);
    #pragma unroll
    for (int i=0;i<CH;i++){
      int idx = st+i;
      if (idx<NN){ indptr[idx]=run; cursor[idx]=run; run+=dv[i]; }
    }
    if (t==1023) indptr[NN] = wtot[31];
  }
  gridbar();
  // phase 4: fill
  for (int e=gtid; e<EP; e+=gsz){
    if (e < EE){
      colGat[atomicAdd(&cursor[ei[EE+e]],1)] = ei[e];
    } else {
      int v = e-EE;
      colGat[atomicAdd(&cursor[v],1)] = v;
    }
  }
}

// --- 128x256-tile tf32 GEMM, 8 warps of 64x64, 3-stage cp.async, fused epi ---
enum { EPI_BIAS=0, EPI_RELU_BN=1, EPI_GIN=2, EPI_RES=3, EPI_POOL=4 };

template<int EPI, bool DUAL>
__global__ __launch_bounds__(256)
void gemm_tc(const float* __restrict__ A,
             const float* __restrict__ B,  const float* __restrict__ bias,
             const float* __restrict__ B2, const float* __restrict__ bias2, float* __restrict__ C2,
             const float* __restrict__ g,   const float* __restrict__ be,
             const float* __restrict__ lng, const float* __restrict__ lnb,
             const float* __restrict__ hres,
             const float* __restrict__ stats, float* __restrict__ statsOut,
             const float* __restrict__ W2pool, float* __restrict__ gatebuf,
             float* __restrict__ C, int K)
{
  extern __shared__ float sm[];
  float* AsP = sm;
  float* BsP = sm + AS_FLOATS;
  int tid = threadIdx.x;
  int lane = tid & 31, w = tid >> 5;
  int warpM = (w >> 2) * 64;
  int warpN = (w & 3) * 64;
  int m0 = blockIdx.x * 128;
  const float* Bp = B; const float* biasp = bias; float* Cp = C;
  if (DUAL && blockIdx.y == 1){ Bp = B2; biasp = bias2; Cp = C2; }
  int tg = lane >> 2, tk = lane & 3;

  float acc[4][8][4];
  #pragma unroll
  for (int i=0;i<4;i++)
    #pragma unroll
    for (int j=0;j<8;j++)
      #pragma unroll
      for (int r=0;r<4;r++) acc[i][j][r]=0.f;

  int rowA  = tid >> 2;
  int k4A   = (tid & 3) * 4;
  int krB = tid >> 4;
  int nbB = (tid & 15)*4;

  uint32_t sA0[3], sA1[3], sB[3];
  #pragma unroll
  for (int s=0;s<3;s++){
    sA0[s] = (uint32_t)__cvta_generic_to_shared(&AsP[s*AS_STRIDE + rowA*20 + k4A]);
    sA1[s] = (uint32_t)__cvta_generic_to_shared(&AsP[s*AS_STRIDE + (rowA+64)*20 + k4A]);
    sB[s]  = (uint32_t)__cvta_generic_to_shared(&BsP[s*BS_STRIDE + krB*264 + nbB]);
  }
  const float* gA0 = A  + (long)(m0+rowA   )*K + k4A;
  const float* gA1 = A  + (long)(m0+rowA+64)*K + k4A;
  const float* gB  = Bp + (long)krB*HD + nbB;

  int nk = K >> 4;
  CP16(sA0[0], gA0); CP16(sA1[0], gA1);
  #pragma unroll
  for (int c4=0;c4<4;c4++) CP16(sB[0] + c4*256, gB + c4*64);
  CP_COMMIT();
  if (nk > 1){
    CP16(sA0[1], gA0+16); CP16(sA1[1], gA1+16);
    const float* gBk = gB + (long)16*HD;
    #pragma unroll
    for (int c4=0;c4<4;c4++) CP16(sB[1] + c4*256, gBk + c4*64);
    CP_COMMIT();
  }

  int st = 0;
  for (int kt=0; kt<nk; kt++){
    if (kt+1 < nk) cp_wait<1>(); else cp_wait<0>();
    __syncthreads();
    if (kt+2 < nk){
      int s2 = st+2; if (s2>=3) s2-=3;
      int kb = (kt+2)<<4;
      CP16(sA0[s2], gA0+kb); CP16(sA1[s2], gA1+kb);
      const float* gBk = gB + (long)kb*HD;
      #pragma unroll
      for (int c4=0;c4<4;c4++) CP16(sB[s2] + c4*256, gBk + c4*64);
      CP_COMMIT();
    }
    const float* Abase = AsP + st*AS_STRIDE;
    const float* Bbase = BsP + st*BS_STRIDE;
    #pragma unroll
    for (int ks=0; ks<2; ks++){
      int k0 = ks*8;
      uint32_t a[4][4], b[8][2];
      #pragma unroll
      for (int i=0;i<4;i++){
        int r = warpM + i*16 + tg;
        a[i][0] = tf32u(Abase[(r  )*20 + k0+tk  ]);
        a[i][1] = tf32u(Abase[(r+8)*20 + k0+tk  ]);
        a[i][2] = tf32u(Abase[(r  )*20 + k0+tk+4]);
        a[i][3] = tf32u(Abase[(r+8)*20 + k0+tk+4]);
      }
      #pragma unroll
      for (int j=0;j<8;j++){
        int c = warpN + j*8 + tg;
        b[j][0] = __float_as_uint(Bbase[(k0+tk  )*264 + c]);
        b[j][1] = __float_as_uint(Bbase[(k0+tk+4)*264 + c]);
      }
      #pragma unroll
      for (int i=0;i<4;i++)
        #pragma unroll
        for (int j=0;j<8;j++)
          asm volatile("mma.sync.aligned.m16n8k8.row.col.f32.tf32.tf32.f32 "
            "{%0,%1,%2,%3}, {%4,%5,%6,%7}, {%8,%9}, {%0,%1,%2,%3};"
            : "+f"(acc[i][j][0]), "+f"(acc[i][j][1]),
              "+f"(acc[i][j][2]), "+f"(acc[i][j][3])
            : "r"(a[i][0]), "r"(a[i][1]), "r"(a[i][2]), "r"(a[i][3]),
              "r"(b[j][0]), "r"(b[j][1]));
    }
    st++; if (st>=3) st-=3;
  }

  // ---- epilogue ----
  const float BNS = rsqrtf(1.0f + 1e-5f);
  float mean=0.f, rdenom=1.f;
  if (EPI==EPI_RES){
    const float inv = 1.0f/((float)NN*(float)HD);
    mean = stats[0]*inv;
    float var = stats[1]*inv - mean*mean;
    rdenom = 1.f/(sqrtf(fmaxf(var,0.f)) + 1e-5f);
  }
  float ssum=0.f, sq=0.f;
  float pgate[4][2];
  if (EPI==EPI_POOL){
    #pragma unroll
    for (int i=0;i<4;i++){ pgate[i][0]=0.f; pgate[i][1]=0.f; }
  }
  #pragma unroll
  for (int j=0;j<8;j++){
    int col = warpN + j*8 + tk*2;
    float b0 = biasp[col], b1 = biasp[col+1];
    float g0=0.f,g1=0.f,e0=0.f,e1=0.f;
    if (EPI==EPI_RELU_BN || EPI==EPI_GIN){
      g0=g[col]*BNS; g1=g[col+1]*BNS; e0=be[col]; e1=be[col+1];
    }
    float lg0=0.f,lg1=0.f,lb0=0.f,lb1=0.f;
    if (EPI==EPI_RES){
      lg0=lng[col]; lg1=lng[col+1]; lb0=lnb[col]; lb1=lnb[col+1];
    }
    float w20=0.f,w21=0.f;
    if (EPI==EPI_POOL){ w20=W2pool[col]; w21=W2pool[col+1]; }
    #pragma unroll
    for (int i=0;i<4;i++){
      #pragma unroll
      for (int h=0;h<2;h++){
        int row = m0 + warpM + i*16 + tg + h*8;
        float v0 = acc[i][j][h*2+0] + b0;
        float v1 = acc[i][j][h*2+1] + b1;
        if (EPI==EPI_RELU_BN){
          v0 = fmaxf(v0,0.f)*g0 + e0;
          v1 = fmaxf(v1,0.f)*g1 + e1;
        } else if (EPI==EPI_GIN){
          v0 = fmaxf(v0,0.f)*g0 + e0; v0 = (v0>0.f)? v0 : 0.2f*v0;
          v1 = fmaxf(v1,0.f)*g1 + e1; v1 = (v1>0.f)? v1 : 0.2f*v1;
          ssum += v0+v1; sq += v0*v0+v1*v1;
        } else if (EPI==EPI_RES){
          float2 hv = *(const float2*)&hres[(long)row*HD + col];
          v0 += (hv.x-mean)*rdenom*lg0 + lb0;
          v1 += (hv.y-mean)*rdenom*lg1 + lb1;
          v0 = (v0>0.f)? v0 : 0.2f*v0;
          v1 = (v1>0.f)? v1 : 0.2f*v1;
        } else if (EPI==EPI_POOL){
          pgate[i][h] += tanhf(v0)*w20 + tanhf(v1)*w21;
        }
        if (EPI!=EPI_POOL)
          *(float2*)&Cp[(long)row*HD + col] = make_float2(v0,v1);
      }
    }
  }
  if (EPI==EPI_GIN){
    #pragma unroll
    for (int off=16; off>0; off>>=1){
      ssum += __shfl_xor_sync(0xffffffffu, ssum, off);
      sq   += __shfl_xor_sync(0xffffffffu, sq,   off);
    }
    if (lane==0){
      atomicAdd(&statsOut[0], ssum);
      atomicAdd(&statsOut[1], sq);
    }
  }
  if (EPI==EPI_POOL){
    #pragma unroll
    for (int i=0;i<4;i++)
      #pragma unroll
      for (int h=0;h<2;h++){
        float p = pgate[i][h];
        p += __shfl_xor_sync(0xffffffffu, p, 1);
        p += __shfl_xor_sync(0xffffffffu, p, 2);
        if (tk==0){
          int row = m0 + warpM + i*16 + tg + h*8;
          atomicAdd(&gatebuf[row], p);
        }
      }
  }
}

// ------- GATv2: 4 warps/node = (edge-half x feature-half), float4 lanes -------
__global__ __launch_bounds__(256)
void gat_kernel(const float4* __restrict__ xl4, const float4* __restrict__ xr4,
                const int* __restrict__ indptr, const int* __restrict__ col,
                const float* __restrict__ att, const float* __restrict__ gbias,
                float* __restrict__ hout){
  __shared__ float part[2][2][32][5];
  int warpid = threadIdx.x >> 5;
  int lane = threadIdx.x & 31;
  int nib = warpid >> 2;
  int sub = warpid & 3;
  int eHalf = sub >> 1;
  int fHalf = sub & 1;
  int w = blockIdx.x*2 + nib;
  int fbase = fHalf*32 + lane;
  const float4* at4 = (const float4*)att;
  float4 a  = at4[fbase];
  float4 xr = xr4[w*64 + fbase];
  float4 acc = make_float4(0,0,0,0);
  float s = 0.f;
  int p0 = indptr[w], p1 = indptr[w+1];
  int mid = p0 + ((p1-p0)+1)/2;
  int jb = eHalf ? mid : p0;
  int je = eHalf ? p1  : mid;
  int j = jb;
  for (; j+1 < je; j += 2){
    int ua = col[j], ub = col[j+1];
    float4 xa = xl4[ua*64 + fbase];
    float4 xb = xl4[ub*64 + fbase];
    float qa, qb, v;
    v = xa.x+xr.x; v = v>0.f?v:0.2f*v; qa  = v*a.x;
    v = xa.y+xr.y; v = v>0.f?v:0.2f*v; qa += v*a.y;
    v = xa.z+xr.z; v = v>0.f?v:0.2f*v; qa += v*a.z;
    v = xa.w+xr.w; v = v>0.f?v:0.2f*v; qa += v*a.w;
    v = xb.x+xr.x; v = v>0.f?v:0.2f*v; qb  = v*a.x;
    v = xb.y+xr.y; v = v>0.f?v:0.2f*v; qb += v*a.y;
    v = xb.z+xr.z; v = v>0.f?v:0.2f*v; qb += v*a.z;
    v = xb.w+xr.w; v = v>0.f?v:0.2f*v; qb += v*a.w;
    qa += __shfl_xor_sync(0xffffffffu,qa,1);
    qb += __shfl_xor_sync(0xffffffffu,qb,1);
    qa += __shfl_xor_sync(0xffffffffu,qa,2);
    qb += __shfl_xor_sync(0xffffffffu,qb,2);
    qa += __shfl_xor_sync(0xffffffffu,qa,4);
    qb += __shfl_xor_sync(0xffffffffu,qb,4);
    float ca = __expf(qa), cb = __expf(qb);
    s += ca;
    acc.x += ca*xa.x; acc.y += ca*xa.y; acc.z += ca*xa.z; acc.w += ca*xa.w;
    s += cb;
    acc.x += cb*xb.x; acc.y += cb*xb.y; acc.z += cb*xb.z; acc.w += cb*xb.w;
  }
  if (j < je){
    int u = col[j];
    float4 x = xl4[u*64 + fbase];
    float q, v;
    v = x.x+xr.x; v = v>0.f?v:0.2f*v; q  = v*a.x;
    v = x.y+xr.y; v = v>0.f?v:0.2f*v; q += v*a.y;
    v = x.z+xr.z; v = v>0.f?v:0.2f*v; q += v*a.z;
    v = x.w+xr.w; v = v>0.f?v:0.2f*v; q += v*a.w;
    q += __shfl_xor_sync(0xffffffffu,q,1);
    q += __shfl_xor_sync(0xffffffffu,q,2);
    q += __shfl_xor_sync(0xffffffffu,q,4);
    float c = __expf(q);
    s += c;
    acc.x += c*x.x; acc.y += c*x.y; acc.z += c*x.z; acc.w += c*x.w;
  }
  if (eHalf == 1){
    part[nib][fHalf][lane][0] = acc.x;
    part[nib][fHalf][lane][1] = acc.y;
    part[nib][fHalf][lane][2] = acc.z;
    part[nib][fHalf][lane][3] = acc.w;
    part[nib][fHalf][lane][4] = s;
  }
  __syncthreads();
  if (eHalf == 0){
    acc.x += part[nib][fHalf][lane][0];
    acc.y += part[nib][fHalf][lane][1];
    acc.z += part[nib][fHalf][lane][2];
    acc.w += part[nib][fHalf][lane][3];
    s     += part[nib][fHalf][lane][4];
    float r = 1.f/(s+1e-16f);
    float4 b = ((const float4*)gbias)[fbase];
    float4 o;
    o.x = acc.x*r + b.x; o.y = acc.y*r + b.y;
    o.z = acc.z*r + b.z; o.w = acc.w*r + b.w;
    ((float4*)hout)[w*64 + fbase] = o;
  }
}

// ---- GIN aggregation via GAT CSR (self-loop in list), 4 warps/node ----
__global__ __launch_bounds__(256)
void ginagg_kernel(const float4* __restrict__ h4, const int* __restrict__ indptr,
                   const int* __restrict__ col, float* __restrict__ tmp){
  __shared__ float part[2][2][32][4];
  int warpid = threadIdx.x >> 5;
  int lane = threadIdx.x & 31;
  int nib = warpid >> 2;
  int sub = warpid & 3;
  int eHalf = sub >> 1;
  int fHalf = sub & 1;
  int w = blockIdx.x*2 + nib;
  int fbase = fHalf*32 + lane;
  float4 acc = make_float4(0,0,0,0);
  int p0 = indptr[w], p1 = indptr[w+1];
  int mid = p0 + ((p1-p0)+1)/2;
  int jb = eHalf ? mid : p0;
  int je = eHalf ? p1  : mid;
  int j = jb;
  for (; j+3 < je; j += 4){
    int u0 = col[j], u1 = col[j+1], u2 = col[j+2], u3 = col[j+3];
    float4 x0 = h4[u0*64 + fbase];
    float4 x1 = h4[u1*64 + fbase];
    float4 x2 = h4[u2*64 + fbase];
    float4 x3 = h4[u3*64 + fbase];
    acc.x+=x0.x; acc.y+=x0.y; acc.z+=x0.z; acc.w+=x0.w;
    acc.x+=x1.x; acc.y+=x1.y; acc.z+=x1.z; acc.w+=x1.w;
    acc.x+=x2.x; acc.y+=x2.y; acc.z+=x2.z; acc.w+=x2.w;
    acc.x+=x3.x; acc.y+=x3.y; acc.z+=x3.z; acc.w+=x3.w;
  }
  for (; j < je; j++){
    int u = col[j];
    float4 x = h4[u*64 + fbase];
    acc.x+=x.x; acc.y+=x.y; acc.z+=x.z; acc.w+=x.w;
  }
  if (eHalf == 1){
    part[nib][fHalf][lane][0]=acc.x;
    part[nib][fHalf][lane][1]=acc.y;
    part[nib][fHalf][lane][2]=acc.z;
    part[nib][fHalf][lane][3]=acc.w;
  }
  __syncthreads();
  if (eHalf == 0){
    acc.x+=part[nib][fHalf][lane][0];
    acc.y+=part[nib][fHalf][lane][1];
    acc.z+=part[nib][fHalf][lane][2];
    acc.w+=part[nib][fHalf][lane][3];
    ((float4*)tmp)[w*64 + fbase] = acc;
  }
}

// ---------------- pooling: batch softmax (single block) ----------------
__global__ void bsoftmax_kernel(float* __restrict__ gate, const int* __restrict__ batch,
                                const float* __restrict__ b2, float* __restrict__ gsum){
  __shared__ float smax[GG], ssum[GG];
  int t = threadIdx.x;  // 1024 threads
  if (t < GG){ smax[t] = -1e30f; ssum[t] = 0.f; }
  __syncthreads();
  float b2v = b2[0];
  for (int v=t; v<NN; v+=1024)
    atomicMaxF(&smax[batch[v]], gate[v]+b2v);
  __syncthreads();
  for (int v=t; v<NN; v+=1024){
    int b = batch[v];
    float e = __expf(gate[v]+b2v - smax[b]);
    gate[v] = e;
    atomicAdd(&ssum[b], e);
  }
  __syncthreads();
  if (t < GG) gsum[t] = ssum[t];
}

__global__ __launch_bounds__(256)
void emb_kernel(const float* __restrict__ gate, const int* __restrict__ batch,
                const float* __restrict__ gsum, const float* __restrict__ h, float* __restrict__ emb){
  int w = (blockIdx.x*blockDim.x + threadIdx.x)>>5;
  int lane = threadIdx.x & 31;
  if (w >= NN) return;
  int b = batch[w];
  float c = gate[w]/(gsum[b]+1e-16f);
  #pragma unroll
  for (int k=0;k<8;k++) atomicAdd(&emb[b*HD + k*32 + lane], c*h[w*HD + k*32 + lane]);
}

// ---------------- label heads: grid (OO,2), 128 thr, hidden-split ----------------
__global__ __launch_bounds__(128)
void head_kernel(const float* __restrict__ emb, const float* __restrict__ W1,
                 const float* __restrict__ b1, const float* __restrict__ g,
                 const float* __restrict__ be, const float* __restrict__ W2,
                 float* __restrict__ out){
  __shared__ float embS[GG*HD];
  __shared__ float sred[GG];
  int o = blockIdx.x;
  int half = blockIdx.y;
  int t = threadIdx.x;
  int hu = half*128 + t;
  for (int i=t;i<GG*HD;i+=128) embS[i]=emb[i];
  if (t < GG) sred[t]=0.f;
  __syncthreads();
  float acc[GG];
  #pragma unroll
  for (int b=0;b<GG;b++) acc[b]=0.f;
  const float* w = W1 + (long)o*HD*256 + hu;
  for (int d=0;d<HD;d++){
    float wv = w[(long)d*256];
    #pragma unroll
    for (int b=0;b<GG;b++) acc[b] += embS[b*HD+d]*wv;
  }
  const float BNS = rsqrtf(1.0f + 1e-5f);
  float bnscale = g[o*256+hu]*BNS;
  float beta = be[o*256+hu];
  float bb1 = b1[o*256+hu];
  float w2 = W2[o*256+hu];
  #pragma unroll
  for (int b=0;b<GG;b++){
    float z = acc[b]+bb1;
    float sv = z/(1.f+__expf(-z));
    float bnv = sv*bnscale + beta;
    atomicAdd(&sred[b], bnv*w2);
  }
  __syncthreads();
  if (t < GG) atomicAdd(&out[t*OO + o], sred[t]);
}

// ---------------- host launch ----------------
extern "C" void kernel_launch(void* const* d_in, const int* in_sizes, int n_in,
                              void* d_out, int out_size) {
  (void)in_sizes; (void)n_in; (void)out_size;
  const float* x      = (const float*)d_in[0];
  const int*   ei     = (const int*)  d_in[1];
  const int*   batch  = (const int*)  d_in[2];
  const float* fp_W   = (const float*)d_in[3];
  const float* fp_b   = (const float*)d_in[4];
  const float* fp_g   = (const float*)d_in[5];
  const float* fp_be  = (const float*)d_in[6];
  const float* gat_Wl = (const float*)d_in[7];
  const float* gat_bl = (const float*)d_in[8];
  const float* gat_Wr = (const float*)d_in[9];
  const float* gat_br = (const float*)d_in[10];
  const float* gat_att= (const float*)d_in[11];
  const float* gat_bias=(const float*)d_in[12];
  const float* gin_W  = (const float*)d_in[13];
  const float* gin_b  = (const float*)d_in[14];
  const float* gin_g  = (const float*)d_in[15];
  const float* gin_be = (const float*)d_in[16];
  const float* ln_g   = (const float*)d_in[17];
  const float* ln_b   = (const float*)d_in[18];
  const float* res_W  = (const float*)d_in[19];
  const float* res_b  = (const float*)d_in[20];
  const float* pool_W1= (const float*)d_in[21];
  const float* pool_b1= (const float*)d_in[22];
  const float* pool_W2= (const float*)d_in[23];
  const float* pool_b2= (const float*)d_in[24];
  const float* head_W1= (const float*)d_in[25];
  const float* head_b1= (const float*)d_in[26];
  const float* head_g = (const float*)d_in[27];
  const float* head_be= (const float*)d_in[28];
  const float* head_W2= (const float*)d_in[29];
  const float* head_b2= (const float*)d_in[30];

  float *h0,*h1,*xl,*xr,*rw,*red,*gate,*gsum,*emb;
  int *degGat,*ptrGat,*curGat,*colGat;
  cudaGetSymbolAddress((void**)&h0, d_h0);
  cudaGetSymbolAddress((void**)&h1, d_h1);
  cudaGetSymbolAddress((void**)&xl, d_xl);
  cudaGetSymbolAddress((void**)&xr, d_xr);
  cudaGetSymbolAddress((void**)&rw, d_rw);
  cudaGetSymbolAddress((void**)&red, d_red);
  cudaGetSymbolAddress((void**)&gate, d_gate);
  cudaGetSymbolAddress((void**)&gsum, d_gsum);
  cudaGetSymbolAddress((void**)&emb, d_emb);
  cudaGetSymbolAddress((void**)&degGat, d_degGat);
  cudaGetSymbolAddress((void**)&ptrGat, d_ptrGat);
  cudaGetSymbolAddress((void**)&curGat, d_curGat);
  cudaGetSymbolAddress((void**)&colGat, d_colGat);

  cudaFuncSetAttribute(gemm_tc<EPI_RELU_BN,false>, cudaFuncAttributeMaxDynamicSharedMemorySize, SMEM_SZ);
  cudaFuncSetAttribute(gemm_tc<EPI_BIAS,true>,     cudaFuncAttributeMaxDynamicSharedMemorySize, SMEM_SZ);
  cudaFuncSetAttribute(gemm_tc<EPI_GIN,false>,     cudaFuncAttributeMaxDynamicSharedMemorySize, SMEM_SZ);
  cudaFuncSetAttribute(gemm_tc<EPI_RES,false>,     cudaFuncAttributeMaxDynamicSharedMemorySize, SMEM_SZ);
  cudaFuncSetAttribute(gemm_tc<EPI_POOL,false>,    cudaFuncAttributeMaxDynamicSharedMemorySize, SMEM_SZ);

  dim3 gg1(NN/128, 1);
  dim3 gg2(NN/128, 2);

  // launch 1: fused CSR build + init + weight rounding (grid-wide ticket barrier)
  csr_kernel<<<CSR_BLOCKS, 1024>>>(ei, degGat, ptrGat, curGat, colGat,
                                   red, emb, gate, (float*)d_out, head_b2,
                                   fp_W, gat_Wl, gat_Wr, gin_W, res_W, pool_W1, rw);
  // launch 2: feature projection
  gemm_tc<EPI_RELU_BN,false><<<gg1,256,SMEM_SZ>>>(x, rw+FPW_OFF, fp_b, nullptr,nullptr,nullptr,
      fp_g, fp_be, nullptr,nullptr,nullptr,nullptr,nullptr,nullptr,nullptr, h0, DIN);

  float* cur = h0;
  float* alt = h1;
  for (int i=0;i<2;i++){
    const float* Wl = rw + WL_OFF + (long)i*HD*HD;
    const float* bl = gat_bl + (long)i*HD;
    const float* Wr = rw + WR_OFF + (long)i*HD*HD;
    const float* br = gat_br + (long)i*HD;
    const float* at = gat_att + (long)i*8*32;
    const float* gb = gat_bias + (long)i*HD;
    const float* gW = rw + GINW_OFF + (long)i*HD*HD;
    const float* gbi= gin_b + (long)i*HD;
    const float* ggm= gin_g + (long)i*HD;
    const float* gbe= gin_be + (long)i*HD;
    const float* lg = ln_g + (long)i*HD;
    const float* lb = ln_b + (long)i*HD;
    const float* rW = rw + RESW_OFF + (long)i*HD*HD;
    const float* rb = res_b + (long)i*HD;

    // launch 3 (i=0): dual GEMM;  launch 4 (i=0): gat  <-- ncu capture target
    gemm_tc<EPI_BIAS,true><<<gg2,256,SMEM_SZ>>>(cur, Wl, bl, Wr, br, xr,
        nullptr,nullptr,nullptr,nullptr,nullptr,nullptr,nullptr,nullptr,nullptr, xl, HD);
    gat_kernel<<<NN/2, 256>>>((const float4*)xl, (const float4*)xr, ptrGat, colGat, at, gb, alt);
    { float* t = cur; cur = alt; alt = t; }

    ginagg_kernel<<<NN/2, 256>>>((const float4*)cur, ptrGat, colGat, xl);
    gemm_tc<EPI_GIN,false><<<gg1,256,SMEM_SZ>>>(xl, gW, gbi, nullptr,nullptr,nullptr,
        ggm, gbe, nullptr,nullptr,nullptr,nullptr, red + 2*i, nullptr,nullptr, alt, HD);
    { float* t = cur; cur = alt; alt = t; }

    gemm_tc<EPI_RES,false><<<gg1,256,SMEM_SZ>>>(cur, rW, rb, nullptr,nullptr,nullptr,
        nullptr,nullptr, lg, lb, cur, red + 2*i, nullptr,nullptr,nullptr, alt, HD);
    { float* t = cur; cur = alt; alt = t; }
  }

  gemm_tc<EPI_POOL,false><<<gg1,256,SMEM_SZ>>>(cur, rw+POOLW_OFF, pool_b1, nullptr,nullptr,nullptr,
      nullptr,nullptr,nullptr,nullptr,nullptr,nullptr,nullptr, pool_W2, gate, nullptr, HD);
  bsoftmax_kernel<<<1, 1024>>>(gate, batch, pool_b2, gsum);
  emb_kernel<<<NN/8, 256>>>(gate, batch, gsum, cur, emb);

  head_kernel<<<dim3(OO,2), 128>>>(emb, head_W1, head_b1, head_g, head_be, head_W2, (float*)d_out);
}